// round 16
// baseline (speedup 1.0000x reference)
#include <cuda_runtime.h>
#include <cuda_fp16.h>
#include <cstdint>

#define B_TOK 2048
#define DIM   1024
#define NEXP  8
#define HID   10240
#define ODIM  1024
#define SLOTS 4096
#define KSPLIT 4
#define EHALF 4   // expert split point for fc1 pipelining

// ---------- device scratch ----------
__device__ __half g_w1f[(size_t)NEXP * HID * DIM];
__device__ __half g_w2f[(size_t)NEXP * ODIM * HID];
__device__ __half g_x2f[(size_t)B_TOK * DIM];
__device__ __half g_hidf[(size_t)SLOTS * HID];
__device__ float g_partial[(size_t)KSPLIT * SLOTS * ODIM];
__device__ int   g_cnt[NEXP];
__device__ int   g_basee[NEXP];
__device__ int   g_fill[NEXP];
__device__ int   g_rowtok[SLOTS];
__device__ float g_gatec[SLOTS];
__device__ int   g_pos[SLOTS];
__device__ int   g_tok_e[SLOTS];
__device__ float g_tok_g[SLOTS];
__device__ int   g_mtmap[64];
__device__ int   g_totalmt;
__device__ int   g_mthalf;    // #slots with expert < EHALF (prefix of g_mtmap)
__device__ int   g_curA;
__device__ int   g_curB;
__device__ int   g_cur2;

__device__ __forceinline__ uint32_t smem_u32(const void* p) {
    uint32_t a;
    asm("{ .reg .u64 t; cvta.to.shared.u64 t, %1; cvt.u32.u64 %0, t; }" : "=r"(a) : "l"(p));
    return a;
}

#define LDSM4(R, ADDR) \
    asm volatile("ldmatrix.sync.aligned.m8n8.x4.shared.b16 {%0,%1,%2,%3}, [%4];" \
                 : "=r"((R)[0]), "=r"((R)[1]), "=r"((R)[2]), "=r"((R)[3]) : "r"(ADDR))

#define CPA16(DST, SRC) \
    asm volatile("cp.async.cg.shared.global [%0], [%1], 16;" :: "r"(DST), "l"(SRC))
#define CPA_COMMIT() asm volatile("cp.async.commit_group;" ::: "memory")
#define CPA_WAIT1()  asm volatile("cp.async.wait_group 1;" ::: "memory")
#define CPA_WAIT0()  asm volatile("cp.async.wait_group 0;" ::: "memory")

__device__ __forceinline__ void mma16816h(float* d, const uint32_t* a, uint32_t b0, uint32_t b1) {
    asm volatile(
        "mma.sync.aligned.m16n8k16.row.col.f32.f16.f16.f32 "
        "{%0,%1,%2,%3},{%4,%5,%6,%7},{%8,%9},{%0,%1,%2,%3};"
        : "+f"(d[0]), "+f"(d[1]), "+f"(d[2]), "+f"(d[3])
        : "r"(a[0]), "r"(a[1]), "r"(a[2]), "r"(a[3]), "r"(b0), "r"(b1));
}

// ---------- fp32 -> fp16 cast ----------
__global__ __launch_bounds__(256) void cvt_kernel(
    const float4* __restrict__ src, uint2* __restrict__ dst, int n4) {
    for (int i = blockIdx.x * 256 + threadIdx.x; i < n4; i += gridDim.x * 256) {
        float4 v = src[i];
        __half2 h01 = __float22half2_rn(make_float2(v.x, v.y));
        __half2 h23 = __float22half2_rn(make_float2(v.z, v.w));
        uint2 o;
        o.x = *reinterpret_cast<uint32_t*>(&h01);
        o.y = *reinterpret_cast<uint32_t*>(&h23);
        dst[i] = o;
    }
}

__global__ void init_kernel() {
    if (threadIdx.x < NEXP) { g_cnt[threadIdx.x] = 0; g_fill[threadIdx.x] = 0; }
    if (threadIdx.x == 0) { g_curA = 0; g_curB = 0; g_cur2 = 0; }
}

__global__ __launch_bounds__(256) void gate_kernel(
    const float* __restrict__ x1, const float* __restrict__ gw, const float* __restrict__ gb) {
    __shared__ float sgw[NEXP * DIM];
    for (int i = threadIdx.x; i < NEXP * DIM; i += 256) sgw[i] = gw[i];
    __syncthreads();
    int warp = threadIdx.x >> 5, lane = threadIdx.x & 31;
    int t = blockIdx.x * 8 + warp;
    float acc[NEXP];
#pragma unroll
    for (int e = 0; e < NEXP; e++) acc[e] = 0.f;
    const float* xr = x1 + (size_t)t * DIM;
    for (int j = lane; j < DIM; j += 32) {
        float xv = xr[j];
#pragma unroll
        for (int e = 0; e < NEXP; e++) acc[e] = fmaf(xv, sgw[e * DIM + j], acc[e]);
    }
#pragma unroll
    for (int off = 16; off > 0; off >>= 1)
#pragma unroll
        for (int e = 0; e < NEXP; e++) acc[e] += __shfl_down_sync(0xFFFFFFFFu, acc[e], off);
    if (lane == 0) {
        float l[NEXP], p[NEXP], m = -1e30f;
#pragma unroll
        for (int e = 0; e < NEXP; e++) { l[e] = acc[e] + gb[e]; m = fmaxf(m, l[e]); }
        float s = 0.f;
#pragma unroll
        for (int e = 0; e < NEXP; e++) { p[e] = expf(l[e] - m); s += p[e]; }
        float inv = 1.f / s;
        int e0 = 0; float v0 = -1.f;
#pragma unroll
        for (int e = 0; e < NEXP; e++) { p[e] *= inv; if (p[e] > v0) { v0 = p[e]; e0 = e; } }
        int e1 = 0; float v1 = -2.f;
#pragma unroll
        for (int e = 0; e < NEXP; e++) if (e != e0 && p[e] > v1) { v1 = p[e]; e1 = e; }
        g_tok_e[2 * t] = e0;     g_tok_g[2 * t] = v0;
        g_tok_e[2 * t + 1] = e1; g_tok_g[2 * t + 1] = v1;
        atomicAdd(&g_cnt[e0], 1);
        atomicAdd(&g_cnt[e1], 1);
    }
}

__global__ void scan_kernel() {
    if (threadIdx.x == 0) {
        int s = 0, slot = 0, half = 0;
        for (int e = 0; e < NEXP; e++) {
            g_basee[e] = s;
            int c = g_cnt[e];
            s += c;
            int nmt = (c + 127) >> 7;
            for (int mt = 0; mt < nmt; mt++) g_mtmap[slot++] = (e << 8) | mt;
            if (e == EHALF - 1) half = slot;
        }
        g_totalmt = slot;
        g_mthalf = half;
    }
}

__global__ void scatter_kernel() {
    int s = blockIdx.x * 256 + threadIdx.x;
    if (s < SLOTS) {
        int e = g_tok_e[s];
        int r = atomicAdd(&g_fill[e], 1);
        int row = g_basee[e] + r;
        g_rowtok[row] = s >> 1;
        g_gatec[row] = g_tok_g[s];
        g_pos[s] = row;
    }
}

// ---------------- grouped GEMM: fp16 single-pass, cp.async 3-stage, worklist ----------------
#define STAGE_B 32768
#define SA 0
#define SB 16384
#define SMEM_TOTAL (1024 + 3 * STAGE_B)

template <int MODE>  // 0: fc1 (x2 -> hidden fp16), 1: fc2 (hidden -> partial fp32)
__global__ __launch_bounds__(256, 2) void moe_gemm(const float* __restrict__ bias, int which) {
    constexpr int K    = MODE ? HID : DIM;
    constexpr int N    = MODE ? ODIM : HID;
    constexpr int NTIL = N / 128;
    constexpr int NC   = MODE ? (HID / KSPLIT / 64) : (DIM / 64);

    const __half* __restrict__ Asrc = MODE ? g_hidf : g_x2f;
    const __half* __restrict__ Bsrc = MODE ? g_w2f : g_w1f;

    extern __shared__ char smem[];
    int* rts = (int*)smem;
    uint32_t stg32 = smem_u32(smem) + 1024;

    int tid = threadIdx.x, l = tid & 31, w = tid >> 5;
    int m0 = (w >> 1) * 32, n0 = (w & 1) * 64;
    int lr = tid >> 1;
    int c16b = (tid & 1) * 4;

    uint32_t dsw[4];
#pragma unroll
    for (int j = 0; j < 4; j++)
        dsw[j] = (uint32_t)lr * 128 + ((((uint32_t)(c16b + j)) * 16) ^ (((uint32_t)lr & 7) << 4));

    uint32_t aArow = m0 + (l & 15), aBrow = n0 + (l & 15);
    uint32_t lxor = ((uint32_t)l & 7) << 4;
    uint32_t khalf = ((uint32_t)l >> 4) * 16;

    // worklist bounds
    int slot_lo, nslots, total;
    int* cur;
    if (MODE == 0) {
        slot_lo = which ? g_mthalf : 0;
        int hi = which ? g_totalmt : g_mthalf;
        nslots = hi - slot_lo;
        total = nslots * NTIL;
        cur = which ? &g_curB : &g_curA;
    } else {
        slot_lo = 0;
        nslots = g_totalmt;
        total = nslots * NTIL * KSPLIT;
        cur = &g_cur2;
    }

    while (true) {
        __syncthreads();
        if (tid == 0) rts[128] = atomicAdd(cur, 1);
        __syncthreads();
        int i = rts[128];
        if (i >= total) break;

        // decode:
        //  fc1: m-slot fastest within half — concurrent CTAs share the B slice
        //  fc2: nt fastest — concurrent CTAs share the A slice
        int slot, nt, ks;
        if (MODE == 0) {
            slot = slot_lo + (i % nslots);
            nt = i / nslots;
            ks = 0;
        } else {
            nt = i & 7;
            ks = (i >> 3) & 3;
            slot = i >> 5;
        }
        int em = g_mtmap[slot];
        int e = em >> 8, mt = em & 255;
        int cnt = g_cnt[e];
        int eb = g_basee[e];
        int mb = mt * 128;
        int rv = cnt - mb; if (rv > 128) rv = 128;
        int nb = nt * 128;
        int kofs = MODE ? ks * (K / KSPLIT) : 0;

        if (MODE == 0) {
            if (tid < 128) {
                int r = tid < rv ? tid : rv - 1;
                rts[tid] = g_rowtok[eb + mb + r];
            }
            __syncthreads();
        }

        const __half* a_p;
        if (MODE == 0) a_p = Asrc + (size_t)rts[lr] * DIM;
        else {
            int r = lr < rv ? lr : rv - 1;
            a_p = Asrc + (size_t)(eb + mb + r) * HID + kofs;
        }
        const __half* b_p = Bsrc + ((size_t)e * N + nb + lr) * K + kofs;

        float acc[2][8][4];
#pragma unroll
        for (int mi = 0; mi < 2; mi++)
#pragma unroll
            for (int ni = 0; ni < 8; ni++)
#pragma unroll
                for (int qq = 0; qq < 4; qq++) acc[mi][ni][qq] = 0.f;

        auto issue = [&](int c) {
            int k0 = c * 64;
            uint32_t ds = stg32 + (c % 3) * STAGE_B;
#pragma unroll
            for (int j = 0; j < 4; j++) {
                int eo = k0 + (c16b + j) * 8;
                uint32_t o = dsw[j];
                CPA16(ds + SA + o, a_p + eo);
                CPA16(ds + SB + o, b_p + eo);
            }
            CPA_COMMIT();
        };

        issue(0);
        issue(1);

        for (int c = 0; c < NC; c++) {
            if (c + 2 < NC) { CPA_WAIT1(); } else { CPA_WAIT0(); }
            __syncthreads();
            if (c + 2 < NC) issue(c + 2);

            uint32_t s32 = stg32 + (c % 3) * STAGE_B;
#pragma unroll
            for (int kt = 0; kt < 4; kt++) {
                uint32_t kb = (((uint32_t)kt * 32) + khalf) ^ lxor;
                uint32_t af[2][4], bf[4][4];
#pragma unroll
                for (int mi = 0; mi < 2; mi++)
                    LDSM4(af[mi], s32 + SA + (aArow + mi * 16) * 128 + kb);
#pragma unroll
                for (int ng = 0; ng < 4; ng++)
                    LDSM4(bf[ng], s32 + SB + (aBrow + ng * 16) * 128 + kb);
#pragma unroll
                for (int mi = 0; mi < 2; mi++)
#pragma unroll
                    for (int ng = 0; ng < 4; ng++)
#pragma unroll
                        for (int p = 0; p < 2; p++)
                            mma16816h(acc[mi][ng * 2 + p], af[mi], bf[ng][p], bf[ng][p + 2]);
            }
        }

        // ---- epilogue ----
        int rbase = eb + mb;
#pragma unroll
        for (int mi = 0; mi < 2; mi++)
#pragma unroll
            for (int h = 0; h < 2; h++) {
                int r = m0 + mi * 16 + (l >> 2) + h * 8;
                if (r >= rv) continue;
                if (MODE == 0) {
                    size_t ro = (size_t)(rbase + r) * HID + nb;
#pragma unroll
                    for (int ni = 0; ni < 8; ni++) {
                        int col = n0 + ni * 8 + (l & 3) * 2;
                        float2 bv = *(const float2*)(bias + (size_t)e * N + nb + col);
                        float2 o;
                        o.x = fmaxf(acc[mi][ni][h * 2 + 0] + bv.x, 0.f);
                        o.y = fmaxf(acc[mi][ni][h * 2 + 1] + bv.y, 0.f);
                        *(__half2*)(g_hidf + ro + col) = __float22half2_rn(o);
                    }
                } else {
                    float gs = g_gatec[rbase + r];
                    float* orow = g_partial + ((size_t)ks * SLOTS + rbase + r) * ODIM + nb;
#pragma unroll
                    for (int ni = 0; ni < 8; ni++) {
                        int col = n0 + ni * 8 + (l & 3) * 2;
                        float2 o;
                        o.x = acc[mi][ni][h * 2 + 0];
                        o.y = acc[mi][ni][h * 2 + 1];
                        if (ks == 0) {
                            float2 bv = *(const float2*)(bias + (size_t)e * N + nb + col);
                            o.x += bv.x; o.y += bv.y;
                        }
                        o.x *= gs; o.y *= gs;
                        *(float2*)(orow + col) = o;
                    }
                }
            }
    }
}

__global__ __launch_bounds__(256) void combine_kernel(float* __restrict__ out) {
    int i = blockIdx.x * 256 + threadIdx.x;
    int t = i >> 8, c = i & 255;
    int p0 = g_pos[2 * t], p1 = g_pos[2 * t + 1];
    const float4* P = (const float4*)g_partial;
    float4 s = make_float4(0.f, 0.f, 0.f, 0.f);
#pragma unroll
    for (int kk = 0; kk < KSPLIT; kk++) {
        float4 a = P[((size_t)kk * SLOTS + p0) * 256 + c];
        float4 b = P[((size_t)kk * SLOTS + p1) * 256 + c];
        s.x += a.x + b.x; s.y += a.y + b.y; s.z += a.z + b.z; s.w += a.w + b.w;
    }
    ((float4*)out)[i] = s;
}

extern "C" void kernel_launch(void* const* d_in, const int* in_sizes, int n_in,
                              void* d_out, int out_size) {
    const float* x1     = (const float*)d_in[0];
    const float* x2     = (const float*)d_in[1];
    const float* gate_w = (const float*)d_in[2];
    const float* gate_b = (const float*)d_in[3];
    const float* fc1_w  = (const float*)d_in[4];
    const float* fc1_b  = (const float*)d_in[5];
    const float* fc2_w  = (const float*)d_in[6];
    const float* fc2_b  = (const float*)d_in[7];

    cudaFuncSetAttribute(moe_gemm<0>, cudaFuncAttributeMaxDynamicSharedMemorySize, SMEM_TOTAL);
    cudaFuncSetAttribute(moe_gemm<1>, cudaFuncAttributeMaxDynamicSharedMemorySize, SMEM_TOTAL);

    __half *w1f, *w2f, *x2f;
    cudaGetSymbolAddress((void**)&w1f, g_w1f);
    cudaGetSymbolAddress((void**)&w2f, g_w2f);
    cudaGetSymbolAddress((void**)&x2f, g_x2f);

    // side stream + events (host resources, created once)
    static cudaStream_t s2 = nullptr;
    static cudaEvent_t ev_a = nullptr, ev_b = nullptr, ev_c = nullptr,
                       ev_w1a = nullptr, ev_w1b = nullptr;
    if (!s2) {
        cudaStreamCreateWithFlags(&s2, cudaStreamNonBlocking);
        cudaEventCreateWithFlags(&ev_a, cudaEventDisableTiming);
        cudaEventCreateWithFlags(&ev_b, cudaEventDisableTiming);
        cudaEventCreateWithFlags(&ev_c, cudaEventDisableTiming);
        cudaEventCreateWithFlags(&ev_w1a, cudaEventDisableTiming);
        cudaEventCreateWithFlags(&ev_w1b, cudaEventDisableTiming);
    }

    const size_t W1_HALF = (size_t)EHALF * HID * DIM;          // elements in expert half
    const int    W1_HALF4 = (int)(W1_HALF / 4);

    // fork: s2 runs routing chain (concurrent with main's cvt passes)
    cudaEventRecord(ev_a, 0);
    cudaStreamWaitEvent(s2, ev_a, 0);

    init_kernel<<<1, 32, 0, s2>>>();
    gate_kernel<<<B_TOK / 8, 256, 0, s2>>>(x1, gate_w, gate_b);
    scan_kernel<<<1, 32, 0, s2>>>();
    scatter_kernel<<<SLOTS / 256, 256, 0, s2>>>();
    cudaEventRecord(ev_b, s2);

    // main: x2 cvt + w1 cvt (experts 0..EHALF-1) at full DRAM bandwidth
    cvt_kernel<<<1024, 256>>>((const float4*)x2, (uint2*)x2f, B_TOK * DIM / 4);
    cvt_kernel<<<2048, 256>>>((const float4*)fc1_w, (uint2*)w1f, W1_HALF4);
    cudaEventRecord(ev_w1a, 0);

    // s2: after w1-A cvt, convert w1-B then w2 — both hidden under fc1's compute
    cudaStreamWaitEvent(s2, ev_w1a, 0);
    cvt_kernel<<<2048, 256, 0, s2>>>((const float4*)(fc1_w + W1_HALF),
                                     (uint2*)(w1f + W1_HALF), W1_HALF4);
    cudaEventRecord(ev_w1b, s2);
    cvt_kernel<<<2048, 256, 0, s2>>>((const float4*)fc2_w, (uint2*)w2f, NEXP * ODIM * HID / 4);
    cudaEventRecord(ev_c, s2);

    // main: fc1_A (experts 0..3) -> fc1_B (experts 4..7, after w1-B cvt) -> fc2 -> combine
    cudaStreamWaitEvent(0, ev_b, 0);
    moe_gemm<0><<<296, 256, SMEM_TOTAL>>>(fc1_b, 0);
    cudaStreamWaitEvent(0, ev_w1b, 0);
    moe_gemm<0><<<296, 256, SMEM_TOTAL>>>(fc1_b, 1);
    cudaStreamWaitEvent(0, ev_c, 0);
    moe_gemm<1><<<296, 256, SMEM_TOTAL>>>(fc2_b, 0);
    combine_kernel<<<(B_TOK * ODIM / 4) / 256, 256>>>((float*)d_out);
}

// round 17
// speedup vs baseline: 1.0199x; 1.0199x over previous
#include <cuda_runtime.h>
#include <cuda_fp16.h>
#include <cstdint>

#define B_TOK 2048
#define DIM   1024
#define NEXP  8
#define HID   10240
#define ODIM  1024
#define SLOTS 4096
#define KSPLIT 4

// ---------- device scratch ----------
__device__ __half g_w1f[(size_t)NEXP * HID * DIM];
__device__ __half g_w2f[(size_t)NEXP * ODIM * HID];
__device__ __half g_x2f[(size_t)B_TOK * DIM];
__device__ __half g_hidf[(size_t)SLOTS * HID];
__device__ float g_partial[(size_t)KSPLIT * SLOTS * ODIM];
__device__ int   g_cnt[NEXP];
__device__ int   g_basee[NEXP];
__device__ int   g_fill[NEXP];
__device__ int   g_rowtok[SLOTS];
__device__ float g_gatec[SLOTS];
__device__ int   g_pos[SLOTS];
__device__ int   g_tok_e[SLOTS];
__device__ float g_tok_g[SLOTS];
__device__ int   g_mtmap[64];
__device__ int   g_totalmt;
__device__ int   g_cur1;
__device__ int   g_cur2;

__device__ __forceinline__ uint32_t smem_u32(const void* p) {
    uint32_t a;
    asm("{ .reg .u64 t; cvta.to.shared.u64 t, %1; cvt.u32.u64 %0, t; }" : "=r"(a) : "l"(p));
    return a;
}

#define LDSM4(R, ADDR) \
    asm volatile("ldmatrix.sync.aligned.m8n8.x4.shared.b16 {%0,%1,%2,%3}, [%4];" \
                 : "=r"((R)[0]), "=r"((R)[1]), "=r"((R)[2]), "=r"((R)[3]) : "r"(ADDR))

#define CPA16(DST, SRC) \
    asm volatile("cp.async.cg.shared.global [%0], [%1], 16;" :: "r"(DST), "l"(SRC))
#define CPA_COMMIT() asm volatile("cp.async.commit_group;" ::: "memory")
#define CPA_WAIT1()  asm volatile("cp.async.wait_group 1;" ::: "memory")
#define CPA_WAIT0()  asm volatile("cp.async.wait_group 0;" ::: "memory")

__device__ __forceinline__ void mma16816h(float* d, const uint32_t* a, uint32_t b0, uint32_t b1) {
    asm volatile(
        "mma.sync.aligned.m16n8k16.row.col.f32.f16.f16.f32 "
        "{%0,%1,%2,%3},{%4,%5,%6,%7},{%8,%9},{%0,%1,%2,%3};"
        : "+f"(d[0]), "+f"(d[1]), "+f"(d[2]), "+f"(d[3])
        : "r"(a[0]), "r"(a[1]), "r"(a[2]), "r"(a[3]), "r"(b0), "r"(b1));
}

// ---------- fp32 -> fp16 cast ----------
__global__ __launch_bounds__(256) void cvt_kernel(
    const float4* __restrict__ src, uint2* __restrict__ dst, int n4) {
    for (int i = blockIdx.x * 256 + threadIdx.x; i < n4; i += gridDim.x * 256) {
        float4 v = src[i];
        __half2 h01 = __float22half2_rn(make_float2(v.x, v.y));
        __half2 h23 = __float22half2_rn(make_float2(v.z, v.w));
        uint2 o;
        o.x = *reinterpret_cast<uint32_t*>(&h01);
        o.y = *reinterpret_cast<uint32_t*>(&h23);
        dst[i] = o;
    }
}

__global__ void init_kernel() {
    if (threadIdx.x < NEXP) { g_cnt[threadIdx.x] = 0; g_fill[threadIdx.x] = 0; }
    if (threadIdx.x == 0) { g_cur1 = 0; g_cur2 = 0; }
}

__global__ __launch_bounds__(256) void gate_kernel(
    const float* __restrict__ x1, const float* __restrict__ gw, const float* __restrict__ gb) {
    __shared__ float sgw[NEXP * DIM];
    for (int i = threadIdx.x; i < NEXP * DIM; i += 256) sgw[i] = gw[i];
    __syncthreads();
    int warp = threadIdx.x >> 5, lane = threadIdx.x & 31;
    int t = blockIdx.x * 8 + warp;
    float acc[NEXP];
#pragma unroll
    for (int e = 0; e < NEXP; e++) acc[e] = 0.f;
    const float* xr = x1 + (size_t)t * DIM;
    for (int j = lane; j < DIM; j += 32) {
        float xv = xr[j];
#pragma unroll
        for (int e = 0; e < NEXP; e++) acc[e] = fmaf(xv, sgw[e * DIM + j], acc[e]);
    }
#pragma unroll
    for (int off = 16; off > 0; off >>= 1)
#pragma unroll
        for (int e = 0; e < NEXP; e++) acc[e] += __shfl_down_sync(0xFFFFFFFFu, acc[e], off);
    if (lane == 0) {
        float l[NEXP], p[NEXP], m = -1e30f;
#pragma unroll
        for (int e = 0; e < NEXP; e++) { l[e] = acc[e] + gb[e]; m = fmaxf(m, l[e]); }
        float s = 0.f;
#pragma unroll
        for (int e = 0; e < NEXP; e++) { p[e] = expf(l[e] - m); s += p[e]; }
        float inv = 1.f / s;
        int e0 = 0; float v0 = -1.f;
#pragma unroll
        for (int e = 0; e < NEXP; e++) { p[e] *= inv; if (p[e] > v0) { v0 = p[e]; e0 = e; } }
        int e1 = 0; float v1 = -2.f;
#pragma unroll
        for (int e = 0; e < NEXP; e++) if (e != e0 && p[e] > v1) { v1 = p[e]; e1 = e; }
        g_tok_e[2 * t] = e0;     g_tok_g[2 * t] = v0;
        g_tok_e[2 * t + 1] = e1; g_tok_g[2 * t + 1] = v1;
        atomicAdd(&g_cnt[e0], 1);
        atomicAdd(&g_cnt[e1], 1);
    }
}

__global__ void scan_kernel() {
    if (threadIdx.x == 0) {
        int s = 0, slot = 0;
        for (int e = 0; e < NEXP; e++) {
            g_basee[e] = s;
            int c = g_cnt[e];
            s += c;
            int nmt = (c + 127) >> 7;
            for (int mt = 0; mt < nmt; mt++) g_mtmap[slot++] = (e << 8) | mt;
        }
        g_totalmt = slot;
    }
}

__global__ void scatter_kernel() {
    int s = blockIdx.x * 256 + threadIdx.x;
    if (s < SLOTS) {
        int e = g_tok_e[s];
        int r = atomicAdd(&g_fill[e], 1);
        int row = g_basee[e] + r;
        g_rowtok[row] = s >> 1;
        g_gatec[row] = g_tok_g[s];
        g_pos[s] = row;
    }
}

// ---------------- grouped GEMM: fp16 single-pass, cp.async 3-stage, worklist ----------------
#define STAGE_B 32768
#define SA 0
#define SB 16384
#define SMEM_TOTAL (1024 + 3 * STAGE_B)

template <int MODE>  // 0: fc1 (x2 -> hidden fp16), 1: fc2 (hidden -> partial fp32)
__global__ __launch_bounds__(256, 2) void moe_gemm(const float* __restrict__ bias) {
    constexpr int K    = MODE ? HID : DIM;
    constexpr int N    = MODE ? ODIM : HID;
    constexpr int NTIL = N / 128;
    constexpr int NC   = MODE ? (HID / KSPLIT / 64) : (DIM / 64);

    const __half* __restrict__ Asrc = MODE ? g_hidf : g_x2f;
    const __half* __restrict__ Bsrc = MODE ? g_w2f : g_w1f;

    extern __shared__ char smem[];
    int* rts = (int*)smem;
    uint32_t stg32 = smem_u32(smem) + 1024;

    int tid = threadIdx.x, l = tid & 31, w = tid >> 5;
    int m0 = (w >> 1) * 32, n0 = (w & 1) * 64;
    int lr = tid >> 1;
    int c16b = (tid & 1) * 4;

    uint32_t dsw[4];
#pragma unroll
    for (int j = 0; j < 4; j++)
        dsw[j] = (uint32_t)lr * 128 + ((((uint32_t)(c16b + j)) * 16) ^ (((uint32_t)lr & 7) << 4));

    uint32_t aArow = m0 + (l & 15), aBrow = n0 + (l & 15);
    uint32_t lxor = ((uint32_t)l & 7) << 4;
    uint32_t khalf = ((uint32_t)l >> 4) * 16;

    const int tot_mt = g_totalmt;
    const int total = tot_mt * (MODE ? NTIL * KSPLIT : NTIL);
    int* cur = MODE ? &g_cur2 : &g_cur1;

    while (true) {
        __syncthreads();
        if (tid == 0) rts[128] = atomicAdd(cur, 1);
        __syncthreads();
        int i = rts[128];
        if (i >= total) break;

        // decode:
        //  fc1 (MODE 0): m-slot fastest — concurrent CTAs share the B slice (A tiny, L2-resident)
        //  fc2 (MODE 1): nt fastest — concurrent CTAs share the A slice
        int slot, nt, ks;
        if (MODE == 0) {
            slot = i % tot_mt;
            nt = i / tot_mt;
            ks = 0;
        } else {
            nt = i & 7;
            ks = (i >> 3) & 3;
            slot = i >> 5;
        }
        int em = g_mtmap[slot];
        int e = em >> 8, mt = em & 255;
        int cnt = g_cnt[e];
        int eb = g_basee[e];
        int mb = mt * 128;
        int rv = cnt - mb; if (rv > 128) rv = 128;
        int nb = nt * 128;
        int kofs = MODE ? ks * (K / KSPLIT) : 0;

        if (MODE == 0) {
            if (tid < 128) {
                int r = tid < rv ? tid : rv - 1;
                rts[tid] = g_rowtok[eb + mb + r];
            }
            __syncthreads();
        }

        const __half* a_p;
        if (MODE == 0) a_p = Asrc + (size_t)rts[lr] * DIM;
        else {
            int r = lr < rv ? lr : rv - 1;
            a_p = Asrc + (size_t)(eb + mb + r) * HID + kofs;
        }
        const __half* b_p = Bsrc + ((size_t)e * N + nb + lr) * K + kofs;

        float acc[2][8][4];
#pragma unroll
        for (int mi = 0; mi < 2; mi++)
#pragma unroll
            for (int ni = 0; ni < 8; ni++)
#pragma unroll
                for (int qq = 0; qq < 4; qq++) acc[mi][ni][qq] = 0.f;

        auto issue = [&](int c) {
            int k0 = c * 64;
            uint32_t ds = stg32 + (c % 3) * STAGE_B;
#pragma unroll
            for (int j = 0; j < 4; j++) {
                int eo = k0 + (c16b + j) * 8;
                uint32_t o = dsw[j];
                CPA16(ds + SA + o, a_p + eo);
                CPA16(ds + SB + o, b_p + eo);
            }
            CPA_COMMIT();
        };

        issue(0);
        issue(1);

        for (int c = 0; c < NC; c++) {
            if (c + 2 < NC) { CPA_WAIT1(); } else { CPA_WAIT0(); }
            __syncthreads();
            if (c + 2 < NC) issue(c + 2);

            uint32_t s32 = stg32 + (c % 3) * STAGE_B;
#pragma unroll
            for (int kt = 0; kt < 4; kt++) {
                uint32_t kb = (((uint32_t)kt * 32) + khalf) ^ lxor;
                uint32_t af[2][4], bf[4][4];
#pragma unroll
                for (int mi = 0; mi < 2; mi++)
                    LDSM4(af[mi], s32 + SA + (aArow + mi * 16) * 128 + kb);
#pragma unroll
                for (int ng = 0; ng < 4; ng++)
                    LDSM4(bf[ng], s32 + SB + (aBrow + ng * 16) * 128 + kb);
#pragma unroll
                for (int mi = 0; mi < 2; mi++)
#pragma unroll
                    for (int ng = 0; ng < 4; ng++)
#pragma unroll
                        for (int p = 0; p < 2; p++)
                            mma16816h(acc[mi][ng * 2 + p], af[mi], bf[ng][p], bf[ng][p + 2]);
            }
        }

        // ---- epilogue ----
        int rbase = eb + mb;
#pragma unroll
        for (int mi = 0; mi < 2; mi++)
#pragma unroll
            for (int h = 0; h < 2; h++) {
                int r = m0 + mi * 16 + (l >> 2) + h * 8;
                if (r >= rv) continue;
                if (MODE == 0) {
                    size_t ro = (size_t)(rbase + r) * HID + nb;
#pragma unroll
                    for (int ni = 0; ni < 8; ni++) {
                        int col = n0 + ni * 8 + (l & 3) * 2;
                        float2 bv = *(const float2*)(bias + (size_t)e * N + nb + col);
                        float2 o;
                        o.x = fmaxf(acc[mi][ni][h * 2 + 0] + bv.x, 0.f);
                        o.y = fmaxf(acc[mi][ni][h * 2 + 1] + bv.y, 0.f);
                        *(__half2*)(g_hidf + ro + col) = __float22half2_rn(o);
                    }
                } else {
                    float gs = g_gatec[rbase + r];
                    float* orow = g_partial + ((size_t)ks * SLOTS + rbase + r) * ODIM + nb;
#pragma unroll
                    for (int ni = 0; ni < 8; ni++) {
                        int col = n0 + ni * 8 + (l & 3) * 2;
                        float2 o;
                        o.x = acc[mi][ni][h * 2 + 0];
                        o.y = acc[mi][ni][h * 2 + 1];
                        if (ks == 0) {
                            float2 bv = *(const float2*)(bias + (size_t)e * N + nb + col);
                            o.x += bv.x; o.y += bv.y;
                        }
                        o.x *= gs; o.y *= gs;
                        *(float2*)(orow + col) = o;
                    }
                }
            }
    }
}

__global__ __launch_bounds__(256) void combine_kernel(float* __restrict__ out) {
    int i = blockIdx.x * 256 + threadIdx.x;
    int t = i >> 8, c = i & 255;
    int p0 = g_pos[2 * t], p1 = g_pos[2 * t + 1];
    const float4* P = (const float4*)g_partial;
    float4 s = make_float4(0.f, 0.f, 0.f, 0.f);
#pragma unroll
    for (int kk = 0; kk < KSPLIT; kk++) {
        float4 a = P[((size_t)kk * SLOTS + p0) * 256 + c];
        float4 b = P[((size_t)kk * SLOTS + p1) * 256 + c];
        s.x += a.x + b.x; s.y += a.y + b.y; s.z += a.z + b.z; s.w += a.w + b.w;
    }
    ((float4*)out)[i] = s;
}

extern "C" void kernel_launch(void* const* d_in, const int* in_sizes, int n_in,
                              void* d_out, int out_size) {
    const float* x1     = (const float*)d_in[0];
    const float* x2     = (const float*)d_in[1];
    const float* gate_w = (const float*)d_in[2];
    const float* gate_b = (const float*)d_in[3];
    const float* fc1_w  = (const float*)d_in[4];
    const float* fc1_b  = (const float*)d_in[5];
    const float* fc2_w  = (const float*)d_in[6];
    const float* fc2_b  = (const float*)d_in[7];

    cudaFuncSetAttribute(moe_gemm<0>, cudaFuncAttributeMaxDynamicSharedMemorySize, SMEM_TOTAL);
    cudaFuncSetAttribute(moe_gemm<1>, cudaFuncAttributeMaxDynamicSharedMemorySize, SMEM_TOTAL);

    __half *w1f, *w2f, *x2f;
    cudaGetSymbolAddress((void**)&w1f, g_w1f);
    cudaGetSymbolAddress((void**)&w2f, g_w2f);
    cudaGetSymbolAddress((void**)&x2f, g_x2f);

    // side stream + events (host resources, created once)
    static cudaStream_t s2 = nullptr;
    static cudaEvent_t ev_a = nullptr, ev_b = nullptr, ev_c = nullptr, ev_w1 = nullptr;
    if (!s2) {
        cudaStreamCreateWithFlags(&s2, cudaStreamNonBlocking);
        cudaEventCreateWithFlags(&ev_a, cudaEventDisableTiming);
        cudaEventCreateWithFlags(&ev_b, cudaEventDisableTiming);
        cudaEventCreateWithFlags(&ev_c, cudaEventDisableTiming);
        cudaEventCreateWithFlags(&ev_w1, cudaEventDisableTiming);
    }

    // fork: s2 runs routing chain + x2 cvt (all off the critical path,
    // concurrent with main's full-bandwidth w1 cvt)
    cudaEventRecord(ev_a, 0);
    cudaStreamWaitEvent(s2, ev_a, 0);

    init_kernel<<<1, 32, 0, s2>>>();
    gate_kernel<<<B_TOK / 8, 256, 0, s2>>>(x1, gate_w, gate_b);
    scan_kernel<<<1, 32, 0, s2>>>();
    scatter_kernel<<<SLOTS / 256, 256, 0, s2>>>();
    cvt_kernel<<<1024, 256, 0, s2>>>((const float4*)x2, (uint2*)x2f, B_TOK * DIM / 4);
    cudaEventRecord(ev_b, s2);   // routing + x2f ready

    // main: w1 cvt at FULL DRAM bandwidth (x2 cvt moved off this path)
    cvt_kernel<<<4096, 256>>>((const float4*)fc1_w, (uint2*)w1f, NEXP * HID * DIM / 4);
    cudaEventRecord(ev_w1, 0);

    // s2: w2 cvt starts only AFTER w1 cvt completes -> overlaps fc1's
    // compute-bound mainloop (DRAM idle there) instead of contending with w1 cvt
    cudaStreamWaitEvent(s2, ev_w1, 0);
    cvt_kernel<<<2048, 256, 0, s2>>>((const float4*)fc2_w, (uint2*)w2f, NEXP * ODIM * HID / 4);
    cudaEventRecord(ev_c, s2);

    // main: fc1 (after routing + x2f), then fc2 (after w2 cvt), combine
    cudaStreamWaitEvent(0, ev_b, 0);
    moe_gemm<0><<<296, 256, SMEM_TOTAL>>>(fc1_b);
    cudaStreamWaitEvent(0, ev_c, 0);
    moe_gemm<1><<<296, 256, SMEM_TOTAL>>>(fc2_b);
    combine_kernel<<<(B_TOK * ODIM / 4) / 256, 256>>>((float*)d_out);
}